// round 1
// baseline (speedup 1.0000x reference)
#include <cuda_runtime.h>
#include <math.h>

// Problem constants
#define TT   256
#define BB   64
#define EE   512
#define HDD  256
#define NGG  1024         // 4*HD
#define KK   7
#define START_TAG 5
#define STOP_TAG  6
#define NEGV (-10000.0f)
#define RR   (TT*BB)      // 16384 rows

// ---------------- scratch (static device memory; no allocation) ----------------
__device__ float g_xg[2u * NGG * RR];       // [2048][16384] gate-major precomputed input gates (128 MiB)
__device__ float g_xmid[(size_t)RR * 512];  // layer-0 output (concat hf|hb)
__device__ float g_xout[(size_t)RR * 512];  // layer-1 output
__device__ float g_h[4 * BB * HDD];         // [dir*2 + parity][64*256] h exchange buffers
__device__ float g_feats[RR * KK];
__device__ unsigned char g_bp[TT * BB * 8]; // viterbi backpointers, padded to 8
__device__ unsigned int g_barcnt[2];        // monotonic, never reset (wrap-safe)
__device__ unsigned int g_barflag[2];       // monotonic, never reset

// =================================================================================
// GEMM: xg[m][r] = bias[m] + sum_k A[m][k] * X[r][k]
//   A = w_ih[layer] flattened [2048][512]; X rows are emb[sent[r]] (layer 0) or
//   g_xmid[r] (layer 1). Output is gate-major [2048][16384] so recurrence reads
//   are coalesced. Tiles 128x128x16, 8x8 microtile, 256 threads.
// =================================================================================
__global__ void __launch_bounds__(256) gemm_xg(
    int layer,
    const int*   __restrict__ sent,
    const float* __restrict__ emb,
    const float* __restrict__ w_ih,
    const float* __restrict__ b_ih,
    const float* __restrict__ b_hh)
{
    __shared__ float As[16][132];
    __shared__ float Bs[16][132];

    const float* A    = w_ih + (size_t)layer * 2 * 1024 * 512;
    const float* bihL = b_ih + layer * 2048;
    const float* bhhL = b_hh + layer * 2048;
    const float* Bsrc;
    const int*   sidx;
    if (layer == 0) { Bsrc = emb;    sidx = sent; }
    else            { Bsrc = g_xmid; sidx = 0;    }

    int tid = threadIdx.x;
    int n0 = blockIdx.x * 128;
    int m0 = blockIdx.y * 128;
    int tx = tid & 15, ty = tid >> 4;

    int ar0 = tid >> 2;
    int ac0 = (tid & 3) * 4;

    // resolve gathered B row pointers once
    int rn0 = n0 + ar0;
    int rn1 = n0 + ar0 + 64;
    const float* brow0 = Bsrc + (size_t)(sidx ? sidx[rn0] : rn0) * 512 + ac0;
    const float* brow1 = Bsrc + (size_t)(sidx ? sidx[rn1] : rn1) * 512 + ac0;
    const float* arow0 = A + (size_t)(m0 + ar0)      * 512 + ac0;
    const float* arow1 = A + (size_t)(m0 + ar0 + 64) * 512 + ac0;

    float acc[8][8];
#pragma unroll
    for (int i = 0; i < 8; i++)
#pragma unroll
        for (int j = 0; j < 8; j++) acc[i][j] = 0.f;

    for (int k0 = 0; k0 < 512; k0 += 16) {
        float4 a0 = *(const float4*)(arow0 + k0);
        float4 a1 = *(const float4*)(arow1 + k0);
        float4 b0 = *(const float4*)(brow0 + k0);
        float4 b1 = *(const float4*)(brow1 + k0);
        __syncthreads();            // previous compute done
        As[ac0+0][ar0]    = a0.x; As[ac0+1][ar0]    = a0.y; As[ac0+2][ar0]    = a0.z; As[ac0+3][ar0]    = a0.w;
        As[ac0+0][ar0+64] = a1.x; As[ac0+1][ar0+64] = a1.y; As[ac0+2][ar0+64] = a1.z; As[ac0+3][ar0+64] = a1.w;
        Bs[ac0+0][ar0]    = b0.x; Bs[ac0+1][ar0]    = b0.y; Bs[ac0+2][ar0]    = b0.z; Bs[ac0+3][ar0]    = b0.w;
        Bs[ac0+0][ar0+64] = b1.x; Bs[ac0+1][ar0+64] = b1.y; Bs[ac0+2][ar0+64] = b1.z; Bs[ac0+3][ar0+64] = b1.w;
        __syncthreads();
#pragma unroll
        for (int kk = 0; kk < 16; kk++) {
            float a[8], b[8];
#pragma unroll
            for (int i = 0; i < 8; i++) a[i] = As[kk][ty*8 + i];
#pragma unroll
            for (int j = 0; j < 8; j++) b[j] = Bs[kk][tx*8 + j];
#pragma unroll
            for (int i = 0; i < 8; i++)
#pragma unroll
                for (int j = 0; j < 8; j++) acc[i][j] += a[i] * b[j];
        }
    }

#pragma unroll
    for (int i = 0; i < 8; i++) {
        int m = m0 + ty*8 + i;
        float bias = __ldg(&bihL[m]) + __ldg(&bhhL[m]);
        float* outp = g_xg + (size_t)m * RR + n0 + tx*8;
#pragma unroll
        for (int j = 0; j < 8; j++) outp[j] = acc[i][j] + bias;
    }
}

// =================================================================================
// Persistent bidirectional LSTM layer. Grid (64, 2): blockIdx.y = direction.
// Each CTA owns 4 h-columns (all 4 gates), 256 threads = 64 batch x 4 cols.
// Per step: load full h into SMEM (L1-bypassed), 4 dots of K=256 per thread,
// gates -> c (register) -> h, write h to double-buffered global + layer output,
// monotonic spin barrier per direction (64 CTAs each, all guaranteed resident).
// =================================================================================
__global__ void __launch_bounds__(256) lstm_layer(
    int layer,
    const float* __restrict__ w_hh,
    const float* __restrict__ h0,
    const float* __restrict__ c0)
{
    extern __shared__ float sm[];
    float* h_s = sm;               // [64][260] padded
    float* w_s = sm + 64 * 260;    // [16][256] : row = q*4 + jl

    const int d   = blockIdx.y;
    const int j0  = blockIdx.x * 4;
    const int tid = threadIdx.x;
    const int b   = tid & 63;
    const int jl  = tid >> 6;
    const int col = j0 + jl;

    float* out_x = layer ? g_xout : g_xmid;
    const float* xg = g_xg + (size_t)d * NGG * RR;

    // stage this CTA's 16 W_hh rows into SMEM
    const float* wl = w_hh + (size_t)(layer*2 + d) * 1024 * 256;
    for (int idx = tid; idx < 16*256; idx += 256) {
        int rr = idx >> 8, k = idx & 255;
        int q = rr >> 2, jj = rr & 3;
        w_s[rr*256 + k] = wl[(size_t)(q*256 + j0 + jj)*256 + k];
    }

    float c = c0[(2*layer + d) * (BB*HDD) + b*HDD + col];

    unsigned fbase = 0;
    if (tid == 0) fbase = atomicAdd(&g_barflag[d], 0u);  // safe: flag advances only after all 64 CTAs arrive

    for (int s = 0; s < TT; ++s) {
        int te  = d ? (TT - 1 - s) : s;
        int row = te * BB + b;

        const float* hsrc = (s == 0) ? (h0 + (2*layer + d) * (BB*HDD))
                                     : (g_h + (size_t)(d*2 + ((s+1)&1)) * (BB*HDD));
        // load h[64][256] -> SMEM, bypassing L1 (written by peer CTAs)
        for (int i = tid; i < 4096; i += 256) {
            float4 v = __ldcg(((const float4*)hsrc) + i);
            int fi = i * 4;
            *(float4*)(h_s + (fi >> 8) * 260 + (fi & 255)) = v;
        }
        // prefetch input gates (read-only, gate-major -> coalesced over b)
        float xgi = __ldg(&xg[(size_t)(0*256 + col) * RR + row]);
        float xgf = __ldg(&xg[(size_t)(1*256 + col) * RR + row]);
        float xgg = __ldg(&xg[(size_t)(2*256 + col) * RR + row]);
        float xgo = __ldg(&xg[(size_t)(3*256 + col) * RR + row]);
        __syncthreads();

        float a0 = 0.f, a1 = 0.f, a2 = 0.f, a3 = 0.f;
        const float* hp = h_s + b * 260;
        const float* w0 = w_s + (0*4 + jl) * 256;
        const float* w1 = w_s + (1*4 + jl) * 256;
        const float* w2 = w_s + (2*4 + jl) * 256;
        const float* w3 = w_s + (3*4 + jl) * 256;
#pragma unroll 8
        for (int k = 0; k < 256; k += 4) {
            float4 hv = *(const float4*)(hp + k);
            float4 v0 = *(const float4*)(w0 + k);
            float4 v1 = *(const float4*)(w1 + k);
            float4 v2 = *(const float4*)(w2 + k);
            float4 v3 = *(const float4*)(w3 + k);
            a0 += hv.x*v0.x + hv.y*v0.y + hv.z*v0.z + hv.w*v0.w;
            a1 += hv.x*v1.x + hv.y*v1.y + hv.z*v1.z + hv.w*v1.w;
            a2 += hv.x*v2.x + hv.y*v2.y + hv.z*v2.z + hv.w*v2.w;
            a3 += hv.x*v3.x + hv.y*v3.y + hv.z*v3.z + hv.w*v3.w;
        }

        float gi = 1.f / (1.f + expf(-(xgi + a0)));
        float gf = 1.f / (1.f + expf(-(xgf + a1)));
        float gg = tanhf(xgg + a2);
        float go = 1.f / (1.f + expf(-(xgo + a3)));
        c = gf * c + gi * gg;
        float h = go * tanhf(c);

        g_h[(size_t)(d*2 + (s & 1)) * (BB*HDD) + b*HDD + col] = h;
        out_x[(size_t)row * 512 + d*256 + col] = h;

        if (s < TT - 1) {
            __threadfence();
            __syncthreads();
            if (tid == 0) {
                unsigned v = atomicAdd(&g_barcnt[d], 1u);
                if ((v & 63u) == 63u)
                    atomicExch(&g_barflag[d], fbase + (unsigned)(s + 1));
                unsigned tgt = (unsigned)(s + 1);
                while ((unsigned)(atomicAdd(&g_barflag[d], 0u) - fbase) < tgt)
                    __nanosleep(32);
            }
            __syncthreads();
        }
    }
}

// =================================================================================
// feats[r][k] = b_out[k] + dot(x2[r], w_out[k]); one warp per tag, 7 warps/row
// =================================================================================
__global__ void feats_kernel(const float* __restrict__ wout,
                             const float* __restrict__ bout)
{
    int r = blockIdx.x;
    int w = threadIdx.x >> 5;         // tag 0..6
    int lane = threadIdx.x & 31;
    const float* xr = g_xout + (size_t)r * 512;
    const float* wr = wout + w * 512;
    float acc = 0.f;
#pragma unroll
    for (int i = 0; i < 16; i++) {
        int e = lane + i * 32;
        acc += xr[e] * wr[e];
    }
#pragma unroll
    for (int o = 16; o; o >>= 1) acc += __shfl_down_sync(0xffffffffu, acc, o);
    if (lane == 0) g_feats[r * KK + w] = acc + bout[w];
}

// =================================================================================
// Viterbi: 448 threads = 64 batch x 7 next-tags; double-buffered v in SMEM,
// backpointers to global (padded rows of 8), then 64-thread backtrack + output.
// =================================================================================
__global__ void viterbi_kernel(const float* __restrict__ trans,
                               void* out, int floatmode)
{
    __shared__ float vbuf[2][64][8];
    __shared__ float tr[7][7];

    int tid = threadIdx.x;
    if (tid < 49) tr[tid / 7][tid % 7] = trans[tid];
    int b  = tid & 63;
    int nx = tid >> 6;                // 0..6
    vbuf[0][b][nx] = (nx == START_TAG) ? 0.f : NEGV;
    __syncthreads();

    int p = 0;
    for (int t = 0; t < TT; ++t) {
        float best = vbuf[p][b][0] + tr[nx][0];
        int   bp   = 0;
#pragma unroll
        for (int pv = 1; pv < 7; ++pv) {
            float cnd = vbuf[p][b][pv] + tr[nx][pv];
            if (cnd > best) { best = cnd; bp = pv; }
        }
        vbuf[p ^ 1][b][nx] = best + g_feats[(t*BB + b) * KK + nx];
        g_bp[(t*BB + b) * 8 + nx] = (unsigned char)bp;
        __syncthreads();
        p ^= 1;
    }

    if (tid < 64) {
        float bestt = vbuf[p][tid][0] + tr[STOP_TAG][0];
        int   lastt = 0;
#pragma unroll
        for (int k2 = 1; k2 < 7; ++k2) {
            float cnd = vbuf[p][tid][k2] + tr[STOP_TAG][k2];
            if (cnd > bestt) { bestt = cnd; lastt = k2; }
        }
        int tag = lastt;
        if (floatmode) {
            float* fo = (float*)out;
            fo[RR + tid] = bestt;
            for (int t = TT - 1; t >= 0; --t) {
                fo[tid * TT + t] = (float)tag;
                tag = g_bp[(t*BB + tid) * 8 + tag];
            }
        } else {
            int* io = (int*)out;
            for (int t = TT - 1; t >= 0; --t) {
                io[tid * TT + t] = tag;
                tag = g_bp[(t*BB + tid) * 8 + tag];
            }
        }
    }
}

// =================================================================================
extern "C" void kernel_launch(void* const* d_in, const int* in_sizes, int n_in,
                              void* d_out, int out_size)
{
    const int*   sent  = (const int*)  d_in[0];
    const float* emb   = (const float*)d_in[1];
    const float* w_ih  = (const float*)d_in[2];
    const float* w_hh  = (const float*)d_in[3];
    const float* b_ih  = (const float*)d_in[4];
    const float* b_hh  = (const float*)d_in[5];
    const float* w_out = (const float*)d_in[6];
    const float* b_out = (const float*)d_in[7];
    const float* trans = (const float*)d_in[8];
    const float* h0    = (const float*)d_in[9];
    const float* c0    = (const float*)d_in[10];

    size_t lsmem = (size_t)(64*260 + 16*256) * sizeof(float);   // ~83 KB
    cudaFuncSetAttribute(lstm_layer, cudaFuncAttributeMaxDynamicSharedMemorySize, (int)lsmem);

    dim3 ggrid(RR/128, 2048/128);   // (128, 16)
    dim3 lgrid(64, 2);

    gemm_xg<<<ggrid, 256>>>(0, sent, emb, w_ih, b_ih, b_hh);
    lstm_layer<<<lgrid, 256, lsmem>>>(0, w_hh, h0, c0);
    gemm_xg<<<ggrid, 256>>>(1, sent, emb, w_ih, b_ih, b_hh);
    lstm_layer<<<lgrid, 256, lsmem>>>(1, w_hh, h0, c0);
    feats_kernel<<<RR, 224>>>(w_out, b_out);

    int floatmode = (out_size == RR + BB) ? 1 : 0;
    viterbi_kernel<<<1, 448>>>(trans, d_out, floatmode);
}